// round 1
// baseline (speedup 1.0000x reference)
#include <cuda_runtime.h>
#include <math.h>
#include <stdint.h>

// Problem dims (fixed by the benchmark shapes)
#define FMH   480
#define FMW   640
#define CCH   128
#define HWPIX (FMH * FMW)           // 307200
#define PACK_STRIDE (3 * CCH)       // 384 floats per pixel
#define N_ITERS 5
#define LAMBDA  0.01
#define FULLMASK 0xffffffffu

// Scratch: [pixel][map(3)][channel(128)] float = 471 MB
__device__ __align__(16) float d_packed[(size_t)HWPIX * PACK_STRIDE];

// Accumulators: [0..5] = g, [6..26] = H upper-tri (row-major pairs i<=j)
__device__ double d_acc[27];
__device__ float  d_R[9];
__device__ float  d_t[3];

// ---------------------------------------------------------------------------
// Init: copy R_init / t_init into state, zero accumulators.
// ---------------------------------------------------------------------------
__global__ void init_state(const float* __restrict__ Rin,
                           const float* __restrict__ tin) {
    int i = threadIdx.x;
    if (i < 9)  d_R[i] = Rin[i];
    if (i < 3)  d_t[i] = tin[i];
    if (i < 27) d_acc[i] = 0.0;
}

// ---------------------------------------------------------------------------
// Pack: transpose [C][H][W] maps (fq, gx, gy) -> d_packed[pixel][map][C].
// Tile 32 pixels x 32 channels through smem; coalesced on both sides.
// ---------------------------------------------------------------------------
__global__ void pack_maps(const float* __restrict__ fq,
                          const float* __restrict__ gx,
                          const float* __restrict__ gy) {
    __shared__ float tile[32][33];
    const int m = blockIdx.z;
    const float* src = (m == 0) ? fq : ((m == 1) ? gx : gy);
    const int p0 = blockIdx.x * 32;
    const int c0 = blockIdx.y * 32;
    const int tx = threadIdx.x;
    const int ty = threadIdx.y;

#pragma unroll
    for (int r = 0; r < 4; r++) {
        int c = c0 + ty + 8 * r;
        tile[ty + 8 * r][tx] = src[(size_t)c * HWPIX + p0 + tx];
    }
    __syncthreads();
#pragma unroll
    for (int r = 0; r < 4; r++) {
        int p = p0 + ty + 8 * r;
        d_packed[(size_t)p * PACK_STRIDE + m * CCH + c0 + tx] = tile[tx][ty + 8 * r];
    }
}

// ---------------------------------------------------------------------------
// One Gauss-Newton accumulation pass. Warp-per-point; lane = 4-channel group.
// Per point: 4 coalesced float4 loads/lane, 5 butterfly reductions, then
// 27 role-distributed contributions accumulated in double per lane.
// ---------------------------------------------------------------------------
__global__ void gn_iter(const float* __restrict__ pts3D,
                        const float* __restrict__ fref,
                        const float* __restrict__ Kmat,
                        const int* __restrict__ imw_p,
                        const int* __restrict__ imh_p,
                        int N) {
    const int lane   = threadIdx.x & 31;
    const int warp   = (blockIdx.x * blockDim.x + threadIdx.x) >> 5;
    const int nwarps = (gridDim.x * blockDim.x) >> 5;

    const int imw = *imw_p;
    const int imh = *imh_p;

    const float fx = Kmat[0], cx = Kmat[2];
    const float fy = Kmat[4], cy = Kmat[5];

    const float R00 = d_R[0], R01 = d_R[1], R02 = d_R[2];
    const float R10 = d_R[3], R11 = d_R[4], R12 = d_R[5];
    const float R20 = d_R[6], R21 = d_R[7], R22 = d_R[8];
    const float t0 = d_t[0], t1 = d_t[1], t2 = d_t[2];

    // Role decode: lane -> (i,j) output index
    const int role = lane;
    int ri = 0, rj = 0;
    if (role < 6) {
        ri = role; rj = role;
    } else if (role < 27) {
        int r = role - 6, i = 0, len = 6;
        while (r >= len) { r -= len; i++; len--; }
        ri = i; rj = i + r;
    }

    double acc = 0.0;

    for (int n = warp; n < N; n += nwarps) {
        const float X = pts3D[3 * n + 0];
        const float Y = pts3D[3 * n + 1];
        const float Z = pts3D[3 * n + 2];
        const float x = R00 * X + R01 * Y + R02 * Z + t0;
        const float y = R10 * X + R11 * Y + R12 * Z + t1;
        const float z = R20 * X + R21 * Y + R22 * Z + t2;

        const float u = fx * x + cx * z;
        const float v = fy * y + cy * z;
        const int px = (int)rintf(u / z) - 1;   // round-half-even matches jnp.round
        const int py = (int)rintf(v / z) - 1;
        if (px < 0 || py < 0 || px >= imw || py >= imh) continue;

        int row = (int)floorf((float)py * (float)FMH / (float)imh);
        row = min(max(row, 0), FMH - 1);
        int col = (int)floorf((float)px * (float)FMW / (float)imw);
        col = min(max(col, 0), FMW - 1);

        const float4* pix = (const float4*)(d_packed + (size_t)(row * FMW + col) * PACK_STRIDE);
        const float4 q  = pix[lane];          // feature_map_query channels
        const float4 g1 = pix[32 + lane];     // grad_x
        const float4 g2 = pix[64 + lane];     // grad_y
        const float4 fr = ((const float4*)(fref + (size_t)n * CCH))[lane];

        const float ex = q.x - fr.x, ey = q.y - fr.y;
        const float ez = q.z - fr.z, ew = q.w - fr.w;

        float a   = g1.x * ex + g1.y * ey + g1.z * ez + g1.w * ew;
        float b   = g2.x * ex + g2.y * ey + g2.z * ez + g2.w * ew;
        float sxx = g1.x * g1.x + g1.y * g1.y + g1.z * g1.z + g1.w * g1.w;
        float sxy = g1.x * g2.x + g1.y * g2.y + g1.z * g2.z + g1.w * g2.w;
        float syy = g2.x * g2.x + g2.y * g2.y + g2.z * g2.z + g2.w * g2.w;

#pragma unroll
        for (int off = 16; off; off >>= 1) {
            a   += __shfl_xor_sync(FULLMASK, a,   off);
            b   += __shfl_xor_sync(FULLMASK, b,   off);
            sxx += __shfl_xor_sync(FULLMASK, sxx, off);
            sxy += __shfl_xor_sync(FULLMASK, sxy, off);
            syy += __shfl_xor_sync(FULLMASK, syy, off);
        }

        // M = J_px_p @ [I | -skew(p3d)]  (2x6). Lane k (k<6) owns column k.
        const float iz  = 1.0f / z;
        const float xiz = x * iz, yiz = y * iz;
        float m0 = 0.f, m1 = 0.f;
        if      (lane == 0) { m0 = fx * iz;                   m1 = 0.f; }
        else if (lane == 1) { m0 = 0.f;                       m1 = fy * iz; }
        else if (lane == 2) { m0 = -fx * xiz * iz;            m1 = -fy * yiz * iz; }
        else if (lane == 3) { m0 = -fx * xiz * yiz;           m1 = -fy * (1.f + yiz * yiz); }
        else if (lane == 4) { m0 = fx * (1.f + xiz * xiz);    m1 = fy * xiz * yiz; }
        else if (lane == 5) { m0 = -fx * yiz;                 m1 = fy * xiz; }

        const float m0i = __shfl_sync(FULLMASK, m0, ri);
        const float m1i = __shfl_sync(FULLMASK, m1, ri);
        const float m0j = __shfl_sync(FULLMASK, m0, rj);
        const float m1j = __shfl_sync(FULLMASK, m1, rj);

        float contrib;
        if (role < 6) contrib = a * m0i + b * m1i;                       // g_k
        else          contrib = sxx * m0i * m0j                          // H_ij
                               + sxy * (m0i * m1j + m1i * m0j)
                               + syy * m1i * m1j;
        if (role < 27) acc += (double)contrib;
    }

    if (role < 27) atomicAdd(&d_acc[role], acc);
}

// ---------------------------------------------------------------------------
// Solve 6x6 damped system, SO(3) exponential, update R/t, zero accumulators.
// Single thread; on the last iteration also writes the 12-float output.
// ---------------------------------------------------------------------------
__global__ void solve_update(float* out, int write_out) {
    double g[6];
    for (int i = 0; i < 6; i++) g[i] = d_acc[i];

    double Hm[6][7];
    {
        double Hs[6][6];
        int idx = 6;
        for (int i = 0; i < 6; i++)
            for (int j = i; j < 6; j++) { Hs[i][j] = Hs[j][i] = d_acc[idx++]; }
        for (int i = 0; i < 6; i++) Hs[i][i] += LAMBDA * (Hs[i][i] + 1e-9);
        for (int i = 0; i < 6; i++) {
            for (int j = 0; j < 6; j++) Hm[i][j] = Hs[i][j];
            Hm[i][6] = -g[i];
        }
    }

    // Gaussian elimination with partial pivoting
    for (int k = 0; k < 6; k++) {
        int piv = k; double mx = fabs(Hm[k][k]);
        for (int r = k + 1; r < 6; r++)
            if (fabs(Hm[r][k]) > mx) { mx = fabs(Hm[r][k]); piv = r; }
        if (piv != k)
            for (int j = k; j < 7; j++) {
                double tmp = Hm[k][j]; Hm[k][j] = Hm[piv][j]; Hm[piv][j] = tmp;
            }
        const double inv = 1.0 / Hm[k][k];
        for (int r = k + 1; r < 6; r++) {
            const double f = Hm[r][k] * inv;
            for (int j = k; j < 7; j++) Hm[r][j] -= f * Hm[k][j];
        }
    }
    double delta[6];
    for (int k = 5; k >= 0; k--) {
        double s = Hm[k][6];
        for (int j = k + 1; j < 6; j++) s -= Hm[k][j] * delta[j];
        delta[k] = s / Hm[k][k];
    }

    // dR = so3exp(delta[3:6])
    const double wx = delta[3], wy = delta[4], wz = delta[5];
    const double th2 = wx * wx + wy * wy + wz * wz + 1e-24;
    const double th  = sqrt(th2);
    const double A = sin(th) / th;
    const double B = (1.0 - cos(th)) / th2;
    double W[3][3]  = { {0.0, -wz, wy}, {wz, 0.0, -wx}, {-wy, wx, 0.0} };
    double W2[3][3];
    for (int i = 0; i < 3; i++)
        for (int j = 0; j < 3; j++) {
            double s = 0.0;
            for (int k = 0; k < 3; k++) s += W[i][k] * W[k][j];
            W2[i][j] = s;
        }
    double dR[3][3];
    for (int i = 0; i < 3; i++)
        for (int j = 0; j < 3; j++)
            dR[i][j] = (i == j ? 1.0 : 0.0) + A * W[i][j] + B * W2[i][j];

    // R = dR @ R ; t = dR @ t + delta[:3]
    double Rold[3][3], told[3];
    for (int i = 0; i < 3; i++) {
        told[i] = (double)d_t[i];
        for (int j = 0; j < 3; j++) Rold[i][j] = (double)d_R[3 * i + j];
    }
    double Rn[3][3], tn[3];
    for (int i = 0; i < 3; i++) {
        double s = 0.0;
        for (int k = 0; k < 3; k++) s += dR[i][k] * told[k];
        tn[i] = s + delta[i];
        for (int j = 0; j < 3; j++) {
            double r = 0.0;
            for (int k = 0; k < 3; k++) r += dR[i][k] * Rold[k][j];
            Rn[i][j] = r;
        }
    }
    for (int i = 0; i < 3; i++) {
        d_t[i] = (float)tn[i];
        for (int j = 0; j < 3; j++) d_R[3 * i + j] = (float)Rn[i][j];
    }

    for (int i = 0; i < 27; i++) d_acc[i] = 0.0;

    if (write_out) {
        for (int i = 0; i < 3; i++)
            for (int j = 0; j < 3; j++) out[3 * i + j] = (float)Rn[i][j];
        out[9]  = (float)tn[0];
        out[10] = (float)tn[1];
        out[11] = (float)tn[2];
    }
}

// ---------------------------------------------------------------------------
extern "C" void kernel_launch(void* const* d_in, const int* in_sizes, int n_in,
                              void* d_out, int out_size) {
    const float* pts3D = (const float*)d_in[0];
    const float* fref  = (const float*)d_in[1];
    const float* fq    = (const float*)d_in[2];
    const float* gx    = (const float*)d_in[3];
    const float* gy    = (const float*)d_in[4];
    const float* Kmat  = (const float*)d_in[5];
    const float* Rin   = (const float*)d_in[6];
    const float* tin   = (const float*)d_in[7];
    const int*   imw   = (const int*)d_in[8];
    const int*   imh   = (const int*)d_in[9];

    const int N = in_sizes[0] / 3;
    float* out = (float*)d_out;

    init_state<<<1, 32>>>(Rin, tin);

    dim3 pb(32, 8);
    dim3 pg(HWPIX / 32, CCH / 32, 3);
    pack_maps<<<pg, pb>>>(fq, gx, gy);

    for (int it = 0; it < N_ITERS; ++it) {
        gn_iter<<<256, 256>>>(pts3D, fref, Kmat, imw, imh, N);
        solve_update<<<1, 1>>>(out, it == N_ITERS - 1 ? 1 : 0);
    }
}

// round 2
// speedup vs baseline: 1.2797x; 1.2797x over previous
#include <cuda_runtime.h>
#include <cuda_fp16.h>
#include <math.h>
#include <stdint.h>

// Problem dims (fixed by the benchmark shapes)
#define FMH   480
#define FMW   640
#define CCH   128
#define HWPIX (FMH * FMW)           // 307200
#define PACKC (3 * CCH)             // 384 halfs per pixel (q | gx | gy)
#define N_ITERS 5
#define LAMBDA  0.01f
#define FULLMASK 0xffffffffu

// Packed scratch: [pixel][map(3)][channel(128)] half = 236 MB
__device__ __align__(16) __half d_packed[(size_t)HWPIX * PACKC];

// Accumulators: [0..5] = g, [6..26] = H upper-tri (i<=j row-major)
__device__ double d_acc[27];
__device__ float  d_R[9];
__device__ float  d_t[3];
__device__ unsigned int d_ctr;

// ---------------------------------------------------------------------------
// Pack: transpose [C][H][W] fp32 maps -> d_packed[pixel][map][C] fp16.
// Also initializes solver state (R, t, accumulators, block counter).
// ---------------------------------------------------------------------------
__global__ void pack_maps(const float* __restrict__ fq,
                          const float* __restrict__ gx,
                          const float* __restrict__ gy,
                          const float* __restrict__ Rin,
                          const float* __restrict__ tin) {
    if (blockIdx.x == 0 && blockIdx.y == 0 && blockIdx.z == 0 && threadIdx.y == 0) {
        int i = threadIdx.x;
        if (i < 9)  d_R[i] = Rin[i];
        if (i < 3)  d_t[i] = tin[i];
        if (i < 27) d_acc[i] = 0.0;
        if (i == 31) d_ctr = 0u;
    }

    __shared__ float tile[32][33];
    const int m = blockIdx.z;
    const float* src = (m == 0) ? fq : ((m == 1) ? gx : gy);
    const int p0 = blockIdx.x * 32;
    const int c0 = blockIdx.y * 32;
    const int tx = threadIdx.x;
    const int ty = threadIdx.y;

#pragma unroll
    for (int r = 0; r < 4; r++) {
        int c = c0 + ty + 8 * r;
        tile[ty + 8 * r][tx] = src[(size_t)c * HWPIX + p0 + tx];
    }
    __syncthreads();
#pragma unroll
    for (int r = 0; r < 4; r++) {
        int p = p0 + ty + 8 * r;
        d_packed[(size_t)p * PACKC + m * CCH + c0 + tx] =
            __float2half_rn(tile[tx][ty + 8 * r]);
    }
}

// ---------------------------------------------------------------------------
// Float 6x6 damped solve + SO(3) update (matches reference float32 math).
// Runs in one thread of the last-finishing block of gn_iter.
// ---------------------------------------------------------------------------
__device__ void solve_and_update(const float* sacc, float* out, int write_out) {
    float Hm[6][7];
    {
        float Hs[6][6];
        int idx = 6;
        for (int i = 0; i < 6; i++)
            for (int j = i; j < 6; j++) { Hs[i][j] = Hs[j][i] = sacc[idx++]; }
        for (int i = 0; i < 6; i++) Hs[i][i] += LAMBDA * (Hs[i][i] + 1e-9f);
        for (int i = 0; i < 6; i++) {
            for (int j = 0; j < 6; j++) Hm[i][j] = Hs[i][j];
            Hm[i][6] = -sacc[i];
        }
    }
    // Gaussian elimination with partial pivoting
    for (int k = 0; k < 6; k++) {
        int piv = k; float mx = fabsf(Hm[k][k]);
        for (int r = k + 1; r < 6; r++)
            if (fabsf(Hm[r][k]) > mx) { mx = fabsf(Hm[r][k]); piv = r; }
        if (piv != k)
            for (int j = k; j < 7; j++) {
                float tmp = Hm[k][j]; Hm[k][j] = Hm[piv][j]; Hm[piv][j] = tmp;
            }
        const float inv = 1.0f / Hm[k][k];
        for (int r = k + 1; r < 6; r++) {
            const float f = Hm[r][k] * inv;
            for (int j = k; j < 7; j++) Hm[r][j] -= f * Hm[k][j];
        }
    }
    float delta[6];
    for (int k = 5; k >= 0; k--) {
        float s = Hm[k][6];
        for (int j = k + 1; j < 6; j++) s -= Hm[k][j] * delta[j];
        delta[k] = s / Hm[k][k];
    }

    // dR = so3exp(delta[3:6])
    const float wx = delta[3], wy = delta[4], wz = delta[5];
    const float th2 = wx * wx + wy * wy + wz * wz + 1e-24f;
    const float th  = sqrtf(th2);
    const float A = sinf(th) / th;
    const float B = (1.0f - cosf(th)) / th2;
    float W[3][3] = { {0.f, -wz, wy}, {wz, 0.f, -wx}, {-wy, wx, 0.f} };
    float W2[3][3];
    for (int i = 0; i < 3; i++)
        for (int j = 0; j < 3; j++) {
            float s = 0.f;
            for (int k = 0; k < 3; k++) s += W[i][k] * W[k][j];
            W2[i][j] = s;
        }
    float dR[3][3];
    for (int i = 0; i < 3; i++)
        for (int j = 0; j < 3; j++)
            dR[i][j] = (i == j ? 1.f : 0.f) + A * W[i][j] + B * W2[i][j];

    float Rold[3][3], told[3];
    for (int i = 0; i < 3; i++) {
        told[i] = d_t[i];
        for (int j = 0; j < 3; j++) Rold[i][j] = d_R[3 * i + j];
    }
    float Rn[3][3], tn[3];
    for (int i = 0; i < 3; i++) {
        float s = 0.f;
        for (int k = 0; k < 3; k++) s += dR[i][k] * told[k];
        tn[i] = s + delta[i];
        for (int j = 0; j < 3; j++) {
            float r = 0.f;
            for (int k = 0; k < 3; k++) r += dR[i][k] * Rold[k][j];
            Rn[i][j] = r;
        }
    }
    for (int i = 0; i < 3; i++) {
        d_t[i] = tn[i];
        for (int j = 0; j < 3; j++) d_R[3 * i + j] = Rn[i][j];
    }
    if (write_out) {
        for (int i = 0; i < 3; i++)
            for (int j = 0; j < 3; j++) out[3 * i + j] = Rn[i][j];
        out[9]  = tn[0];
        out[10] = tn[1];
        out[11] = tn[2];
    }
}

// ---------------------------------------------------------------------------
// One Gauss-Newton pass, with the 6x6 solve fused into the last block.
// Warp-per-point; lane = 4-channel group for gathers, lane = role for outputs.
// ---------------------------------------------------------------------------
__global__ void gn_iter(const float* __restrict__ pts3D,
                        const float* __restrict__ fref,
                        const float* __restrict__ Kmat,
                        const int* __restrict__ imw_p,
                        const int* __restrict__ imh_p,
                        int N, float* out, int write_out) {
    __shared__ double sacc[27];
    if (threadIdx.x < 27) sacc[threadIdx.x] = 0.0;
    __syncthreads();

    const int lane   = threadIdx.x & 31;
    const int warp   = (blockIdx.x * blockDim.x + threadIdx.x) >> 5;
    const int nwarps = (gridDim.x * blockDim.x) >> 5;

    const int imw = *imw_p;
    const int imh = *imh_p;

    const float fx = Kmat[0], cx = Kmat[2];
    const float fy = Kmat[4], cy = Kmat[5];

    const float R00 = d_R[0], R01 = d_R[1], R02 = d_R[2];
    const float R10 = d_R[3], R11 = d_R[4], R12 = d_R[5];
    const float R20 = d_R[6], R21 = d_R[7], R22 = d_R[8];
    const float t0 = d_t[0], t1 = d_t[1], t2 = d_t[2];

    // Role decode: lane -> output index (0..5 g, 6..26 H_ij upper tri)
    const int role = lane;
    int ri = 0, rj = 0;
    if (role < 6) { ri = role; rj = role; }
    else if (role < 27) {
        int r = role - 6, i = 0, len = 6;
        while (r >= len) { r -= len; i++; len--; }
        ri = i; rj = i + r;
    }

    double acc = 0.0;

    for (int n = warp; n < N; n += nwarps) {
        const float X = pts3D[3 * n + 0];
        const float Y = pts3D[3 * n + 1];
        const float Z = pts3D[3 * n + 2];
        const float x = R00 * X + R01 * Y + R02 * Z + t0;
        const float y = R10 * X + R11 * Y + R12 * Z + t1;
        const float z = R20 * X + R21 * Y + R22 * Z + t2;

        const float u = fx * x + cx * z;
        const float v = fy * y + cy * z;
        const int px = (int)rintf(u / z) - 1;   // round-half-even == jnp.round
        const int py = (int)rintf(v / z) - 1;
        if (px < 0 || py < 0 || px >= imw || py >= imh) continue;

        int row = (int)floorf((float)py * (float)FMH / (float)imh);
        row = min(max(row, 0), FMH - 1);
        int col = (int)floorf((float)px * (float)FMW / (float)imw);
        col = min(max(col, 0), FMW - 1);

        const __half* pix = d_packed + (size_t)(row * FMW + col) * PACKC;
        const uint2 qr = ((const uint2*)pix)[lane];               // 4 q channels
        const uint2 xr = ((const uint2*)(pix + CCH))[lane];       // 4 gx channels
        const uint2 yr = ((const uint2*)(pix + 2 * CCH))[lane];   // 4 gy channels
        const float4 fr = ((const float4*)(fref + (size_t)n * CCH))[lane];

        const float2 q0 = __half22float2(*(const __half2*)&qr.x);
        const float2 q1 = __half22float2(*(const __half2*)&qr.y);
        const float2 x0 = __half22float2(*(const __half2*)&xr.x);
        const float2 x1 = __half22float2(*(const __half2*)&xr.y);
        const float2 y0 = __half22float2(*(const __half2*)&yr.x);
        const float2 y1 = __half22float2(*(const __half2*)&yr.y);

        const float ex = q0.x - fr.x, ey = q0.y - fr.y;
        const float ez = q1.x - fr.z, ew = q1.y - fr.w;

        float a   = x0.x * ex + x0.y * ey + x1.x * ez + x1.y * ew;
        float b   = y0.x * ex + y0.y * ey + y1.x * ez + y1.y * ew;
        float sxx = x0.x * x0.x + x0.y * x0.y + x1.x * x1.x + x1.y * x1.y;
        float sxy = x0.x * y0.x + x0.y * y0.y + x1.x * y1.x + x1.y * y1.y;
        float syy = y0.x * y0.x + y0.y * y0.y + y1.x * y1.x + y1.y * y1.y;

#pragma unroll
        for (int off = 16; off; off >>= 1) {
            a   += __shfl_xor_sync(FULLMASK, a,   off);
            b   += __shfl_xor_sync(FULLMASK, b,   off);
            sxx += __shfl_xor_sync(FULLMASK, sxx, off);
            sxy += __shfl_xor_sync(FULLMASK, sxy, off);
            syy += __shfl_xor_sync(FULLMASK, syy, off);
        }

        // M = J_px_p @ [I | -skew(p3d)]  (2x6). Lane k<6 owns column k.
        const float iz  = 1.0f / z;
        const float xiz = x * iz, yiz = y * iz;
        float m0 = 0.f, m1 = 0.f;
        if      (lane == 0) { m0 = fx * iz;                 m1 = 0.f; }
        else if (lane == 1) { m0 = 0.f;                     m1 = fy * iz; }
        else if (lane == 2) { m0 = -fx * xiz * iz;          m1 = -fy * yiz * iz; }
        else if (lane == 3) { m0 = -fx * xiz * yiz;         m1 = -fy * (1.f + yiz * yiz); }
        else if (lane == 4) { m0 = fx * (1.f + xiz * xiz);  m1 = fy * xiz * yiz; }
        else if (lane == 5) { m0 = -fx * yiz;               m1 = fy * xiz; }

        const float m0i = __shfl_sync(FULLMASK, m0, ri);
        const float m1i = __shfl_sync(FULLMASK, m1, ri);
        const float m0j = __shfl_sync(FULLMASK, m0, rj);
        const float m1j = __shfl_sync(FULLMASK, m1, rj);

        float contrib;
        if (role < 6) contrib = a * m0i + b * m1i;                       // g_k
        else          contrib = sxx * m0i * m0j                          // H_ij
                               + sxy * (m0i * m1j + m1i * m0j)
                               + syy * m1i * m1j;
        if (role < 27) acc += (double)contrib;
    }

    if (role < 27) atomicAdd(&sacc[role], acc);
    __syncthreads();
    if (threadIdx.x < 27) atomicAdd(&d_acc[threadIdx.x], sacc[threadIdx.x]);
    __threadfence();

    __shared__ unsigned int slast;
    if (threadIdx.x == 0) slast = atomicAdd(&d_ctr, 1u);
    __syncthreads();

    if (slast == gridDim.x - 1) {   // last block: fused solve + update
        __shared__ float sH[27];
        if (threadIdx.x < 27) {
            double v = atomicAdd(&d_acc[threadIdx.x], 0.0);  // coherent read
            sH[threadIdx.x] = (float)v;
            d_acc[threadIdx.x] = 0.0;                        // reset for next iter
        }
        __syncthreads();
        if (threadIdx.x == 0) {
            d_ctr = 0u;
            solve_and_update(sH, out, write_out);
        }
    }
}

// ---------------------------------------------------------------------------
extern "C" void kernel_launch(void* const* d_in, const int* in_sizes, int n_in,
                              void* d_out, int out_size) {
    const float* pts3D = (const float*)d_in[0];
    const float* fref  = (const float*)d_in[1];
    const float* fq    = (const float*)d_in[2];
    const float* gx    = (const float*)d_in[3];
    const float* gy    = (const float*)d_in[4];
    const float* Kmat  = (const float*)d_in[5];
    const float* Rin   = (const float*)d_in[6];
    const float* tin   = (const float*)d_in[7];
    const int*   imw   = (const int*)d_in[8];
    const int*   imh   = (const int*)d_in[9];

    const int N = in_sizes[0] / 3;
    float* out = (float*)d_out;

    dim3 pb(32, 8);
    dim3 pg(HWPIX / 32, CCH / 32, 3);
    pack_maps<<<pg, pb>>>(fq, gx, gy, Rin, tin);

    for (int it = 0; it < N_ITERS; ++it) {
        gn_iter<<<256, 256>>>(pts3D, fref, Kmat, imw, imh, N,
                              out, it == N_ITERS - 1 ? 1 : 0);
    }
}

// round 3
// speedup vs baseline: 1.6636x; 1.3000x over previous
#include <cuda_runtime.h>
#include <cuda_fp16.h>
#include <math.h>
#include <stdint.h>

#define FMH   480
#define FMW   640
#define CCH   128
#define HWPIX (FMH * FMW)           // 307200
#define N_ITERS 5
#define LAMBDA  0.01f
#define FULLMASK 0xffffffffu
#define GN_BLOCKS 1024

// Packed gradients: [pixel][c] = half2(gx, gy)  -> 512B/pixel, 157 MB
__device__ __align__(16) __half2 d_packed[(size_t)HWPIX * CCH];
// Per-pixel scalars: [pixel][8] = {A, B, Sxx, Sxy, Syy, pad...} fp32, 32B/pixel
__device__ __align__(16) float d_scal[(size_t)HWPIX * 8];
// fp16 copy of feature_ref [N][128]
__device__ __align__(16) __half d_fref16[(size_t)32768 * CCH];

// Accumulators: [0..5] = g, [6..26] = H upper-tri (i<=j row-major)
__device__ double d_acc[27];
__device__ float  d_R[9];
__device__ float  d_t[3];
__device__ unsigned int d_ctr;

// ---------------------------------------------------------------------------
// fref fp32 -> fp16
// ---------------------------------------------------------------------------
__global__ void quant_fref(const float* __restrict__ fref, int total) {
    int i = blockIdx.x * blockDim.x + threadIdx.x;
    if (4 * i < total) {
        float4 v = ((const float4*)fref)[i];
        __half2* dst = (__half2*)(d_fref16 + 4 * i);
        dst[0] = __floats2half2_rn(v.x, v.y);
        dst[1] = __floats2half2_rn(v.z, v.w);
    }
}

// ---------------------------------------------------------------------------
// Pack: per block, 32 pixels x all 128 channels x 3 maps.
// Emits: d_packed (transposed fp16 gx/gy pairs) and d_scal (5 fp32 scalars).
// Also initializes solver state in block 0.
// ---------------------------------------------------------------------------
__global__ void pack_maps(const float* __restrict__ fq,
                          const float* __restrict__ gx,
                          const float* __restrict__ gy,
                          const float* __restrict__ Rin,
                          const float* __restrict__ tin) {
    if (blockIdx.x == 0 && threadIdx.y == 0) {
        int i = threadIdx.x;
        if (i < 9)  d_R[i] = Rin[i];
        if (i < 3)  d_t[i] = tin[i];
        if (i < 27) d_acc[i] = 0.0;
        if (i == 31) d_ctr = 0u;
    }

    __shared__ __half2 tstage[32][33];        // [c_in_chunk][pixel]
    __shared__ float   rsum[8][32][5];        // [ty][pixel][scalar]

    const int tx = threadIdx.x;               // pixel within tile
    const int ty = threadIdx.y;
    const int p0 = blockIdx.x * 32;

    float pA = 0.f, pB = 0.f, pXX = 0.f, pXY = 0.f, pYY = 0.f;

#pragma unroll
    for (int r = 0; r < 4; r++) {             // 32-channel chunks
#pragma unroll
        for (int s = 0; s < 4; s++) {
            const int c = r * 32 + ty + 8 * s;
            const size_t off = (size_t)c * HWPIX + p0 + tx;
            const float q  = fq[off];
            const float vx = gx[off];
            const float vy = gy[off];
            pA  += vx * q;  pB  += vy * q;
            pXX += vx * vx; pXY += vx * vy; pYY += vy * vy;
            tstage[ty + 8 * s][tx] = __floats2half2_rn(vx, vy);
        }
        __syncthreads();
#pragma unroll
        for (int s = 0; s < 4; s++) {
            const int p = p0 + ty + 8 * s;
            d_packed[(size_t)p * CCH + r * 32 + tx] = tstage[tx][ty + 8 * s];
        }
        __syncthreads();
    }

    rsum[ty][tx][0] = pA;  rsum[ty][tx][1] = pB;
    rsum[ty][tx][2] = pXX; rsum[ty][tx][3] = pXY; rsum[ty][tx][4] = pYY;
    __syncthreads();
    if (ty == 0) {
        float s0 = 0.f, s1 = 0.f, s2 = 0.f, s3 = 0.f, s4 = 0.f;
#pragma unroll
        for (int k = 0; k < 8; k++) {
            s0 += rsum[k][tx][0]; s1 += rsum[k][tx][1];
            s2 += rsum[k][tx][2]; s3 += rsum[k][tx][3]; s4 += rsum[k][tx][4];
        }
        float* dst = d_scal + (size_t)(p0 + tx) * 8;
        ((float4*)dst)[0] = make_float4(s0, s1, s2, s3);
        ((float4*)dst)[1] = make_float4(s4, 0.f, 0.f, 0.f);
    }
}

// ---------------------------------------------------------------------------
// Float 6x6 damped solve + SO(3) update (matches reference float32 math).
// ---------------------------------------------------------------------------
__device__ void solve_and_update(const float* sacc, float* out, int write_out) {
    float Hm[6][7];
    {
        float Hs[6][6];
        int idx = 6;
        for (int i = 0; i < 6; i++)
            for (int j = i; j < 6; j++) { Hs[i][j] = Hs[j][i] = sacc[idx++]; }
        for (int i = 0; i < 6; i++) Hs[i][i] += LAMBDA * (Hs[i][i] + 1e-9f);
        for (int i = 0; i < 6; i++) {
            for (int j = 0; j < 6; j++) Hm[i][j] = Hs[i][j];
            Hm[i][6] = -sacc[i];
        }
    }
    for (int k = 0; k < 6; k++) {
        int piv = k; float mx = fabsf(Hm[k][k]);
        for (int r = k + 1; r < 6; r++)
            if (fabsf(Hm[r][k]) > mx) { mx = fabsf(Hm[r][k]); piv = r; }
        if (piv != k)
            for (int j = k; j < 7; j++) {
                float tmp = Hm[k][j]; Hm[k][j] = Hm[piv][j]; Hm[piv][j] = tmp;
            }
        const float inv = 1.0f / Hm[k][k];
        for (int r = k + 1; r < 6; r++) {
            const float f = Hm[r][k] * inv;
            for (int j = k; j < 7; j++) Hm[r][j] -= f * Hm[k][j];
        }
    }
    float delta[6];
    for (int k = 5; k >= 0; k--) {
        float s = Hm[k][6];
        for (int j = k + 1; j < 6; j++) s -= Hm[k][j] * delta[j];
        delta[k] = s / Hm[k][k];
    }

    const float wx = delta[3], wy = delta[4], wz = delta[5];
    const float th2 = wx * wx + wy * wy + wz * wz + 1e-24f;
    const float th  = sqrtf(th2);
    const float A = sinf(th) / th;
    const float B = (1.0f - cosf(th)) / th2;
    float W[3][3] = { {0.f, -wz, wy}, {wz, 0.f, -wx}, {-wy, wx, 0.f} };
    float W2[3][3];
    for (int i = 0; i < 3; i++)
        for (int j = 0; j < 3; j++) {
            float s = 0.f;
            for (int k = 0; k < 3; k++) s += W[i][k] * W[k][j];
            W2[i][j] = s;
        }
    float dR[3][3];
    for (int i = 0; i < 3; i++)
        for (int j = 0; j < 3; j++)
            dR[i][j] = (i == j ? 1.f : 0.f) + A * W[i][j] + B * W2[i][j];

    float Rold[3][3], told[3];
    for (int i = 0; i < 3; i++) {
        told[i] = d_t[i];
        for (int j = 0; j < 3; j++) Rold[i][j] = d_R[3 * i + j];
    }
    float Rn[3][3], tn[3];
    for (int i = 0; i < 3; i++) {
        float s = 0.f;
        for (int k = 0; k < 3; k++) s += dR[i][k] * told[k];
        tn[i] = s + delta[i];
        for (int j = 0; j < 3; j++) {
            float r = 0.f;
            for (int k = 0; k < 3; k++) r += dR[i][k] * Rold[k][j];
            Rn[i][j] = r;
        }
    }
    for (int i = 0; i < 3; i++) {
        d_t[i] = tn[i];
        for (int j = 0; j < 3; j++) d_R[3 * i + j] = Rn[i][j];
    }
    if (write_out) {
        for (int i = 0; i < 3; i++)
            for (int j = 0; j < 3; j++) out[3 * i + j] = Rn[i][j];
        out[9]  = tn[0];
        out[10] = tn[1];
        out[11] = tn[2];
    }
}

// ---------------------------------------------------------------------------
// One Gauss-Newton pass; 6x6 solve fused into the last-finishing block.
// Warp-per-point. Per point: one 16B gather/lane (4 half2 grad pairs),
// 8B fref16/lane, one 32B scalar sector, 2 butterfly reductions.
// ---------------------------------------------------------------------------
__global__ void gn_iter(const float* __restrict__ pts3D,
                        const float* __restrict__ Kmat,
                        const int* __restrict__ imw_p,
                        const int* __restrict__ imh_p,
                        int N, float* out, int write_out) {
    __shared__ double sacc[27];
    if (threadIdx.x < 27) sacc[threadIdx.x] = 0.0;
    __syncthreads();

    const int lane   = threadIdx.x & 31;
    const int warp   = (blockIdx.x * blockDim.x + threadIdx.x) >> 5;
    const int nwarps = (gridDim.x * blockDim.x) >> 5;

    const int imw = *imw_p;
    const int imh = *imh_p;

    const float fx = Kmat[0], cx = Kmat[2];
    const float fy = Kmat[4], cy = Kmat[5];

    const float R00 = d_R[0], R01 = d_R[1], R02 = d_R[2];
    const float R10 = d_R[3], R11 = d_R[4], R12 = d_R[5];
    const float R20 = d_R[6], R21 = d_R[7], R22 = d_R[8];
    const float t0 = d_t[0], t1 = d_t[1], t2 = d_t[2];

    // Role decode: lane -> output index (0..5 g, 6..26 H_ij upper tri)
    const int role = lane;
    int ri = 0, rj = 0;
    if (role < 6) { ri = role; rj = role; }
    else if (role < 27) {
        int r = role - 6, i = 0, len = 6;
        while (r >= len) { r -= len; i++; len--; }
        ri = i; rj = i + r;
    }

    double acc = 0.0;

    for (int n = warp; n < N; n += nwarps) {
        const float X = pts3D[3 * n + 0];
        const float Y = pts3D[3 * n + 1];
        const float Z = pts3D[3 * n + 2];
        const float x = R00 * X + R01 * Y + R02 * Z + t0;
        const float y = R10 * X + R11 * Y + R12 * Z + t1;
        const float z = R20 * X + R21 * Y + R22 * Z + t2;

        const float u = fx * x + cx * z;
        const float v = fy * y + cy * z;
        const int px = (int)rintf(u / z) - 1;   // round-half-even == jnp.round
        const int py = (int)rintf(v / z) - 1;
        if (px < 0 || py < 0 || px >= imw || py >= imh) continue;

        int row = (int)floorf((float)py * (float)FMH / (float)imh);
        row = min(max(row, 0), FMH - 1);
        int col = (int)floorf((float)px * (float)FMW / (float)imw);
        col = min(max(col, 0), FMW - 1);
        const int pidx = row * FMW + col;

        // gradient pairs: 4 channels per lane
        const uint4 pk = ((const uint4*)(d_packed + (size_t)pidx * CCH))[lane];
        const uint2 fr = ((const uint2*)(d_fref16 + (size_t)n * CCH))[lane];

        const float2 g0 = __half22float2(*(const __half2*)&pk.x);
        const float2 g1 = __half22float2(*(const __half2*)&pk.y);
        const float2 g2 = __half22float2(*(const __half2*)&pk.z);
        const float2 g3 = __half22float2(*(const __half2*)&pk.w);
        const float2 f0 = __half22float2(*(const __half2*)&fr.x);
        const float2 f1 = __half22float2(*(const __half2*)&fr.y);

        float dotx = g0.x * f0.x + g1.x * f0.y + g2.x * f1.x + g3.x * f1.y;
        float doty = g0.y * f0.x + g1.y * f0.y + g2.y * f1.x + g3.y * f1.y;

#pragma unroll
        for (int off = 16; off; off >>= 1) {
            dotx += __shfl_xor_sync(FULLMASK, dotx, off);
            doty += __shfl_xor_sync(FULLMASK, doty, off);
        }

        // per-pixel scalars (one 32B sector)
        const float sv = (lane < 5) ? d_scal[(size_t)pidx * 8 + lane] : 0.f;
        const float a   = __shfl_sync(FULLMASK, sv, 0) - dotx;   // A - gx.fref
        const float b   = __shfl_sync(FULLMASK, sv, 1) - doty;   // B - gy.fref
        const float sxx = __shfl_sync(FULLMASK, sv, 2);
        const float sxy = __shfl_sync(FULLMASK, sv, 3);
        const float syy = __shfl_sync(FULLMASK, sv, 4);

        // M = J_px_p @ [I | -skew(p3d)]  (2x6). Lane k<6 owns column k.
        const float iz  = 1.0f / z;
        const float xiz = x * iz, yiz = y * iz;
        float m0 = 0.f, m1 = 0.f;
        if      (lane == 0) { m0 = fx * iz;                 m1 = 0.f; }
        else if (lane == 1) { m0 = 0.f;                     m1 = fy * iz; }
        else if (lane == 2) { m0 = -fx * xiz * iz;          m1 = -fy * yiz * iz; }
        else if (lane == 3) { m0 = -fx * xiz * yiz;         m1 = -fy * (1.f + yiz * yiz); }
        else if (lane == 4) { m0 = fx * (1.f + xiz * xiz);  m1 = fy * xiz * yiz; }
        else if (lane == 5) { m0 = -fx * yiz;               m1 = fy * xiz; }

        const float m0i = __shfl_sync(FULLMASK, m0, ri);
        const float m1i = __shfl_sync(FULLMASK, m1, ri);
        const float m0j = __shfl_sync(FULLMASK, m0, rj);
        const float m1j = __shfl_sync(FULLMASK, m1, rj);

        float contrib;
        if (role < 6) contrib = a * m0i + b * m1i;                       // g_k
        else          contrib = sxx * m0i * m0j                          // H_ij
                               + sxy * (m0i * m1j + m1i * m0j)
                               + syy * m1i * m1j;
        if (role < 27) acc += (double)contrib;
    }

    if (role < 27) atomicAdd(&sacc[role], acc);
    __syncthreads();
    if (threadIdx.x < 27) atomicAdd(&d_acc[threadIdx.x], sacc[threadIdx.x]);
    __threadfence();

    __shared__ unsigned int slast;
    if (threadIdx.x == 0) slast = atomicAdd(&d_ctr, 1u);
    __syncthreads();

    if (slast == gridDim.x - 1) {   // last block: fused solve + update
        __shared__ float sH[27];
        if (threadIdx.x < 27) {
            double vv = atomicAdd(&d_acc[threadIdx.x], 0.0);  // coherent read
            sH[threadIdx.x] = (float)vv;
            d_acc[threadIdx.x] = 0.0;                         // reset for next iter
        }
        __syncthreads();
        if (threadIdx.x == 0) {
            d_ctr = 0u;
            solve_and_update(sH, out, write_out);
        }
    }
}

// ---------------------------------------------------------------------------
extern "C" void kernel_launch(void* const* d_in, const int* in_sizes, int n_in,
                              void* d_out, int out_size) {
    const float* pts3D = (const float*)d_in[0];
    const float* fref  = (const float*)d_in[1];
    const float* fq    = (const float*)d_in[2];
    const float* gx    = (const float*)d_in[3];
    const float* gy    = (const float*)d_in[4];
    const float* Kmat  = (const float*)d_in[5];
    const float* Rin   = (const float*)d_in[6];
    const float* tin   = (const float*)d_in[7];
    const int*   imw   = (const int*)d_in[8];
    const int*   imh   = (const int*)d_in[9];

    const int N = in_sizes[0] / 3;
    float* out = (float*)d_out;

    const int ftotal = in_sizes[1];
    quant_fref<<<(ftotal / 4 + 255) / 256, 256>>>(fref, ftotal);

    dim3 pb(32, 8);
    pack_maps<<<HWPIX / 32, pb>>>(fq, gx, gy, Rin, tin);

    for (int it = 0; it < N_ITERS; ++it) {
        gn_iter<<<GN_BLOCKS, 256>>>(pts3D, Kmat, imw, imh, N,
                                    out, it == N_ITERS - 1 ? 1 : 0);
    }
}